// round 9
// baseline (speedup 1.0000x reference)
#include <cuda_runtime.h>
#include <cuda_bf16.h>

// ---------------------------------------------------------------------------
// QuantizedLinear: out = x @ quantize(W)^T + bias
// quantize(w) = clamp(ceil(w - 0.5), -4, 3)   (== jnp argmin with first-index ties)
// W = randn*0.1 -> nonzero quantized entries need |w| >= 5 sigma -> nnz ~ 10.
//   k_quant_fill: blocks [0,WB) quantize W + collect nonzeros (atomic counter);
//                 blocks [WB,grid) fill out with bias (streaming float4 stores).
//   k_apply:      rank-nnz update, parallel over (entry x row) jointly so all
//                 ~nnz*B scattered loads/atomics are in flight at once;
//                 guarded dense tiled-GEMM fallback if nnz > cap (never taken);
//                 last-finishing block resets the counter for the next replay.
// ---------------------------------------------------------------------------

#define NNZ_CAP (1 << 20)   // 1M entries = 8 MB scratch
#define SMEM_E  2048        // entries staged in smem per block in k_apply

__device__ int          g_nnz;               // zero-init; reset by k_apply
__device__ unsigned int g_done;              // ticket for last-block reset
__device__ unsigned int g_eidx[NNZ_CAP];     // o*IN + i
__device__ float        g_eval[NNZ_CAP];     // quantized level (nonzero)

__device__ __forceinline__ float quant1(float w) {
    float q = ceilf(w - 0.5f);               // round-half-down, exact vs argmin
    return fmaxf(-4.0f, fminf(3.0f, q));
}

__global__ void k_quant_fill(const float* __restrict__ weight,
                             const float* __restrict__ bias,
                             float* __restrict__ out,
                             int IN, int OUT, int B, int wblocks) {
    if ((int)blockIdx.x < wblocks) {
        // ---- quantize + collect nonzeros (read 64 MB) ----
        const unsigned Wn = (unsigned)OUT * (unsigned)IN;
        const unsigned W4 = Wn >> 2;
        const unsigned gid = blockIdx.x * blockDim.x + threadIdx.x;
        const unsigned stride = (unsigned)wblocks * blockDim.x;
        const float4* w4p = reinterpret_cast<const float4*>(weight);
        for (unsigned t = gid; t < W4; t += stride) {
            float4 w = __ldcs(&w4p[t]);      // streaming: no reuse
            float q0 = quant1(w.x), q1 = quant1(w.y);
            float q2 = quant1(w.z), q3 = quant1(w.w);
            if ((q0 != 0.f) | (q1 != 0.f) | (q2 != 0.f) | (q3 != 0.f)) {
                unsigned base = t << 2;
                if (q0 != 0.f) { int s = atomicAdd(&g_nnz, 1); if (s < NNZ_CAP) { g_eidx[s] = base + 0u; g_eval[s] = q0; } }
                if (q1 != 0.f) { int s = atomicAdd(&g_nnz, 1); if (s < NNZ_CAP) { g_eidx[s] = base + 1u; g_eval[s] = q1; } }
                if (q2 != 0.f) { int s = atomicAdd(&g_nnz, 1); if (s < NNZ_CAP) { g_eidx[s] = base + 2u; g_eval[s] = q2; } }
                if (q3 != 0.f) { int s = atomicAdd(&g_nnz, 1); if (s < NNZ_CAP) { g_eidx[s] = base + 3u; g_eval[s] = q3; } }
            }
        }
        unsigned tail = Wn & 3u;             // no-op for 4096-divisible shapes
        if (gid < tail) {
            unsigned e = (W4 << 2) + gid;
            float q = quant1(weight[e]);
            if (q != 0.f) { int s = atomicAdd(&g_nnz, 1); if (s < NNZ_CAP) { g_eidx[s] = e; g_eval[s] = q; } }
        }
    } else {
        // ---- fill out with broadcast bias (write 128 MB, streaming) ----
        const unsigned gid = (blockIdx.x - wblocks) * blockDim.x + threadIdx.x;
        const unsigned stride = (gridDim.x - wblocks) * blockDim.x;
        if ((OUT & 3) == 0) {
            const unsigned O4 = ((unsigned)B * (unsigned)OUT) >> 2;
            const unsigned OUT4 = (unsigned)OUT >> 2;
            const float4* b4 = reinterpret_cast<const float4*>(bias);
            float4* o4 = reinterpret_cast<float4*>(out);
            if ((OUT4 & (OUT4 - 1)) == 0) {          // power of two: mask
                const unsigned mask = OUT4 - 1;
                for (unsigned t = gid; t < O4; t += stride)
                    __stcs(&o4[t], __ldg(&b4[t & mask]));
            } else {
                for (unsigned t = gid; t < O4; t += stride)
                    __stcs(&o4[t], __ldg(&b4[t % OUT4]));
            }
        } else {                                      // generic scalar path
            const unsigned On = (unsigned)B * (unsigned)OUT;
            for (unsigned t = gid; t < On; t += stride)
                out[t] = __ldg(&bias[t % (unsigned)OUT]);
        }
    }
}

// Sparse apply (normal path) + dense fallback (guarded) + counter reset.
__global__ void k_apply(const float* __restrict__ x,
                        const float* __restrict__ weight,
                        const float* __restrict__ bias,
                        float* __restrict__ out,
                        int IN, int OUT, int B) {
    const int nnz = g_nnz;

    if (nnz <= NNZ_CAP) {
        // Joint (entry, row) parallelization: all scattered ops in flight.
        __shared__ unsigned s_o[SMEM_E];   // output column per entry
        __shared__ unsigned s_i[SMEM_E];   // input column per entry
        __shared__ float    s_v[SMEM_E];

        const bool in_pow2 = ((unsigned)IN & ((unsigned)IN - 1u)) == 0u;
        unsigned in_shift = 0;
        if (in_pow2) { unsigned v = (unsigned)IN; while (v > 1u) { v >>= 1u; in_shift++; } }
        const unsigned in_mask = (unsigned)IN - 1u;

        const unsigned nthreads = gridDim.x * blockDim.x;
        const unsigned gid = blockIdx.x * blockDim.x + threadIdx.x;

        for (int e0 = 0; e0 < nnz; e0 += SMEM_E) {
            const int ecnt = min(nnz - e0, SMEM_E);
            for (int e = threadIdx.x; e < ecnt; e += blockDim.x) {
                unsigned idx = g_eidx[e0 + e];
                s_v[e] = g_eval[e0 + e];
                if (in_pow2) { s_o[e] = idx >> in_shift; s_i[e] = idx & in_mask; }
                else         { s_o[e] = idx / (unsigned)IN; s_i[e] = idx % (unsigned)IN; }
            }
            __syncthreads();

            // work items: item = e * B + b
            const size_t items = (size_t)ecnt * (unsigned)B;
            for (size_t t = gid; t < items; t += nthreads) {
                unsigned e = (unsigned)(t / (unsigned)B);
                unsigned b = (unsigned)(t % (unsigned)B);
                atomicAdd(&out[(size_t)b * OUT + s_o[e]],
                          s_v[e] * __ldg(&x[(size_t)b * IN + s_i[e]]));
            }
            __syncthreads();
        }
    } else {
        // Dense tiled-GEMM safety net (only if scratch overflowed; never taken
        // on this dataset — correct but slow by design).
        const int TM = 64, TN = 64, TK = 16;
        __shared__ float xs[16][64];
        __shared__ float ws[16][64];
        int tid = threadIdx.x;
        int tx = tid & 15, ty = tid >> 4;
        int tilesM = (B + TM - 1) / TM;
        int tilesN = (OUT + TN - 1) / TN;
        for (int tile = blockIdx.x; tile < tilesM * tilesN; tile += gridDim.x) {
            int tm = tile / tilesN, tn = tile % tilesN;
            int m0 = tm * TM, n0 = tn * TN;
            float acc[4][4];
            #pragma unroll
            for (int i2 = 0; i2 < 4; i2++)
                #pragma unroll
                for (int j = 0; j < 4; j++) acc[i2][j] = 0.0f;
            for (int k0 = 0; k0 < IN; k0 += TK) {
                #pragma unroll
                for (int r = 0; r < 4; r++) {
                    int li = tid + r * 256;
                    int k = li >> 6, mm = li & 63;
                    int gk = k0 + k, gm = m0 + mm, gn = n0 + mm;
                    xs[k][mm] = (gm < B && gk < IN) ? x[(size_t)gm * IN + gk] : 0.0f;
                    ws[k][mm] = (gn < OUT && gk < IN) ? quant1(weight[(size_t)gn * IN + gk]) : 0.0f;
                }
                __syncthreads();
                #pragma unroll
                for (int k = 0; k < TK; k++) {
                    float a[4], bb[4];
                    #pragma unroll
                    for (int i2 = 0; i2 < 4; i2++) a[i2] = xs[k][ty * 4 + i2];
                    #pragma unroll
                    for (int j = 0; j < 4; j++) bb[j] = ws[k][tx * 4 + j];
                    #pragma unroll
                    for (int i2 = 0; i2 < 4; i2++)
                        #pragma unroll
                        for (int j = 0; j < 4; j++) acc[i2][j] += a[i2] * bb[j];
                }
                __syncthreads();
            }
            #pragma unroll
            for (int i2 = 0; i2 < 4; i2++) {
                int gm = m0 + ty * 4 + i2;
                if (gm >= B) continue;
                #pragma unroll
                for (int j = 0; j < 4; j++) {
                    int gn = n0 + tx * 4 + j;
                    if (gn < OUT)
                        out[(size_t)gm * OUT + gn] = acc[i2][j] + __ldg(&bias[gn]);
                }
            }
        }
    }

    // Last-finishing block resets the counter for the next graph replay.
    // Safe: every block read g_nnz before incrementing the ticket.
    __syncthreads();
    if (threadIdx.x == 0) {
        unsigned t = atomicAdd(&g_done, 1u);
        if (t == gridDim.x - 1) { g_done = 0u; g_nnz = 0; }
    }
}

extern "C" void kernel_launch(void* const* d_in, const int* in_sizes, int n_in,
                              void* d_out, int out_size) {
    const float* x      = (const float*)d_in[0];   // [B, IN]
    const float* weight = (const float*)d_in[1];   // [OUT, IN]
    const float* bias   = (const float*)d_in[2];   // [OUT]
    float* out = (float*)d_out;                    // [B, OUT]

    int OUT = in_sizes[2];
    int IN  = in_sizes[1] / OUT;
    int B   = in_sizes[0] / IN;

    // Blocks split proportional to traffic: W read 64 MB : out write 128 MB.
    const int grid = 1184;                // 8 blocks/SM on 148 SMs
    const int wblocks = grid / 3;         // ~395 quantize, ~789 fill

    k_quant_fill<<<grid, 256>>>(weight, bias, out, IN, OUT, B, wblocks);
    k_apply<<<1184, 256>>>(x, weight, bias, out, IN, OUT, B);
}

// round 10
// speedup vs baseline: 1.0209x; 1.0209x over previous
#include <cuda_runtime.h>
#include <cuda_bf16.h>

// ---------------------------------------------------------------------------
// QuantizedLinear: out = x @ quantize(W)^T + bias
// quantize(w) = clamp(ceil(w - 0.5), -4, 3)   (== jnp argmin with first-index ties)
// W = randn*0.1 -> nonzero quantized entries need |w| >= 5 sigma -> nnz ~ 10.
//   k_quant_fill: blocks [0,WB) quantize W + collect nonzeros (atomic counter);
//                 blocks [WB,grid) fill out with bias (streaming float4 stores).
//   k_apply:      2D grid (row-blocks x entry-slots); one thread = one
//                 (row, entry) item: ld x, fma, REDG atomicAdd. No smem, no
//                 syncs, single wave. Guarded dense tiled-GEMM fallback if
//                 nnz > cap (never taken). Last block resets the counter.
// ---------------------------------------------------------------------------

#define NNZ_CAP  (1 << 20)   // 1M entries = 8 MB scratch
#define ESLOTS   16          // parallel entry slots (gridDim.y)

__device__ int          g_nnz;               // zero-init; reset by k_apply
__device__ unsigned int g_done;              // ticket for last-block reset
__device__ unsigned int g_eidx[NNZ_CAP];     // o*IN + i
__device__ float        g_eval[NNZ_CAP];     // quantized level (nonzero)

__device__ __forceinline__ float quant1(float w) {
    float q = ceilf(w - 0.5f);               // round-half-down, exact vs argmin
    return fmaxf(-4.0f, fminf(3.0f, q));
}

__global__ void k_quant_fill(const float* __restrict__ weight,
                             const float* __restrict__ bias,
                             float* __restrict__ out,
                             int IN, int OUT, int B, int wblocks) {
    if ((int)blockIdx.x < wblocks) {
        // ---- quantize + collect nonzeros (read 64 MB) ----
        const unsigned Wn = (unsigned)OUT * (unsigned)IN;
        const unsigned W4 = Wn >> 2;
        const unsigned gid = blockIdx.x * blockDim.x + threadIdx.x;
        const unsigned stride = (unsigned)wblocks * blockDim.x;
        const float4* w4p = reinterpret_cast<const float4*>(weight);
        for (unsigned t = gid; t < W4; t += stride) {
            float4 w = __ldcs(&w4p[t]);      // streaming: no reuse
            float q0 = quant1(w.x), q1 = quant1(w.y);
            float q2 = quant1(w.z), q3 = quant1(w.w);
            if ((q0 != 0.f) | (q1 != 0.f) | (q2 != 0.f) | (q3 != 0.f)) {
                unsigned base = t << 2;
                if (q0 != 0.f) { int s = atomicAdd(&g_nnz, 1); if (s < NNZ_CAP) { g_eidx[s] = base + 0u; g_eval[s] = q0; } }
                if (q1 != 0.f) { int s = atomicAdd(&g_nnz, 1); if (s < NNZ_CAP) { g_eidx[s] = base + 1u; g_eval[s] = q1; } }
                if (q2 != 0.f) { int s = atomicAdd(&g_nnz, 1); if (s < NNZ_CAP) { g_eidx[s] = base + 2u; g_eval[s] = q2; } }
                if (q3 != 0.f) { int s = atomicAdd(&g_nnz, 1); if (s < NNZ_CAP) { g_eidx[s] = base + 3u; g_eval[s] = q3; } }
            }
        }
        unsigned tail = Wn & 3u;             // no-op for 4096-divisible shapes
        if (gid < tail) {
            unsigned e = (W4 << 2) + gid;
            float q = quant1(weight[e]);
            if (q != 0.f) { int s = atomicAdd(&g_nnz, 1); if (s < NNZ_CAP) { g_eidx[s] = e; g_eval[s] = q; } }
        }
    } else {
        // ---- fill out with broadcast bias (write 128 MB, streaming) ----
        const unsigned gid = (blockIdx.x - wblocks) * blockDim.x + threadIdx.x;
        const unsigned stride = (gridDim.x - wblocks) * blockDim.x;
        if ((OUT & 3) == 0) {
            const unsigned O4 = ((unsigned)B * (unsigned)OUT) >> 2;
            const unsigned OUT4 = (unsigned)OUT >> 2;
            const float4* b4 = reinterpret_cast<const float4*>(bias);
            float4* o4 = reinterpret_cast<float4*>(out);
            if ((OUT4 & (OUT4 - 1)) == 0) {          // power of two: mask
                const unsigned mask = OUT4 - 1;
                for (unsigned t = gid; t < O4; t += stride)
                    __stcs(&o4[t], __ldg(&b4[t & mask]));
            } else {
                for (unsigned t = gid; t < O4; t += stride)
                    __stcs(&o4[t], __ldg(&b4[t % OUT4]));
            }
        } else {                                      // generic scalar path
            const unsigned On = (unsigned)B * (unsigned)OUT;
            for (unsigned t = gid; t < On; t += stride)
                out[t] = __ldg(&bias[t % (unsigned)OUT]);
        }
    }
}

// Sparse apply (normal path) + dense fallback (guarded) + counter reset.
// Launched with grid (ceil(B/256), ESLOTS), 256 threads.
__global__ void k_apply(const float* __restrict__ x,
                        const float* __restrict__ weight,
                        const float* __restrict__ bias,
                        float* __restrict__ out,
                        int IN, int OUT, int B) {
    const int nnz = g_nnz;

    if (nnz <= NNZ_CAP) {
        // One (row, entry) item per thread; loop only if nnz > ESLOTS.
        const unsigned b = blockIdx.x * blockDim.x + threadIdx.x;
        if (b < (unsigned)B) {
            const unsigned in_pow2 = (((unsigned)IN & ((unsigned)IN - 1u)) == 0u);
            const float* xr = x + (size_t)b * IN;
            float*      orw = out + (size_t)b * OUT;
            for (int e = blockIdx.y; e < nnz; e += ESLOTS) {
                const unsigned idx = __ldg(&g_eidx[e]);   // warp-uniform bcast
                const float v = __ldg(&g_eval[e]);
                unsigned o, i;
                if (in_pow2) {
                    o = idx / (unsigned)IN;               // compiles to shifts
                    i = idx & ((unsigned)IN - 1u);
                } else {
                    o = idx / (unsigned)IN;
                    i = idx % (unsigned)IN;
                }
                atomicAdd(&orw[o], v * __ldg(&xr[i]));    // fire-and-forget
            }
        }
    } else if (blockIdx.y == 0) {
        // Dense tiled-GEMM safety net (only if scratch overflowed; never taken
        // on this dataset — correct but slow by design).
        const int TM = 64, TN = 64, TK = 16;
        __shared__ float xs[16][64];
        __shared__ float ws[16][64];
        int tid = threadIdx.x;
        int tx = tid & 15, ty = tid >> 4;
        int tilesM = (B + TM - 1) / TM;
        int tilesN = (OUT + TN - 1) / TN;
        for (int tile = blockIdx.x; tile < tilesM * tilesN; tile += gridDim.x) {
            int tm = tile / tilesN, tn = tile % tilesN;
            int m0 = tm * TM, n0 = tn * TN;
            float acc[4][4];
            #pragma unroll
            for (int i2 = 0; i2 < 4; i2++)
                #pragma unroll
                for (int j = 0; j < 4; j++) acc[i2][j] = 0.0f;
            for (int k0 = 0; k0 < IN; k0 += TK) {
                #pragma unroll
                for (int r = 0; r < 4; r++) {
                    int li = tid + r * 256;
                    int k = li >> 6, mm = li & 63;
                    int gk = k0 + k, gm = m0 + mm, gn = n0 + mm;
                    xs[k][mm] = (gm < B && gk < IN) ? x[(size_t)gm * IN + gk] : 0.0f;
                    ws[k][mm] = (gn < OUT && gk < IN) ? quant1(weight[(size_t)gn * IN + gk]) : 0.0f;
                }
                __syncthreads();
                #pragma unroll
                for (int k = 0; k < TK; k++) {
                    float a[4], bb[4];
                    #pragma unroll
                    for (int i2 = 0; i2 < 4; i2++) a[i2] = xs[k][ty * 4 + i2];
                    #pragma unroll
                    for (int j = 0; j < 4; j++) bb[j] = ws[k][tx * 4 + j];
                    #pragma unroll
                    for (int i2 = 0; i2 < 4; i2++)
                        #pragma unroll
                        for (int j = 0; j < 4; j++) acc[i2][j] += a[i2] * bb[j];
                }
                __syncthreads();
            }
            #pragma unroll
            for (int i2 = 0; i2 < 4; i2++) {
                int gm = m0 + ty * 4 + i2;
                if (gm >= B) continue;
                #pragma unroll
                for (int j = 0; j < 4; j++) {
                    int gn = n0 + tx * 4 + j;
                    if (gn < OUT)
                        out[(size_t)gm * OUT + gn] = acc[i2][j] + __ldg(&bias[gn]);
                }
            }
        }
    }

    // Last-finishing block resets the counter for the next graph replay.
    // Every block read g_nnz before incrementing the ticket, so the reset
    // happens only after all reads; launch boundary orders it vs next call.
    __syncthreads();
    if (threadIdx.x == 0) {
        unsigned nblocks = gridDim.x * gridDim.y;
        unsigned t = atomicAdd(&g_done, 1u);
        if (t == nblocks - 1) { g_done = 0u; g_nnz = 0; }
    }
}

extern "C" void kernel_launch(void* const* d_in, const int* in_sizes, int n_in,
                              void* d_out, int out_size) {
    const float* x      = (const float*)d_in[0];   // [B, IN]
    const float* weight = (const float*)d_in[1];   // [OUT, IN]
    const float* bias   = (const float*)d_in[2];   // [OUT]
    float* out = (float*)d_out;                    // [B, OUT]

    int OUT = in_sizes[2];
    int IN  = in_sizes[1] / OUT;
    int B   = in_sizes[0] / IN;

    // Blocks split proportional to traffic: W read 64 MB : out write 128 MB.
    const int grid = 1184;                // 8 blocks/SM on 148 SMs
    const int wblocks = grid / 3;         // ~395 quantize, ~789 fill

    k_quant_fill<<<grid, 256>>>(weight, bias, out, IN, OUT, B, wblocks);

    dim3 agrid((B + 255) / 256, ESLOTS);
    k_apply<<<agrid, 256>>>(x, weight, bias, out, IN, OUT, B);
}

// round 11
// speedup vs baseline: 1.2121x; 1.1873x over previous
#include <cuda_runtime.h>
#include <cuda_bf16.h>

// ---------------------------------------------------------------------------
// QuantizedLinear: out = x @ quantize(W)^T + bias
// quantize(w) = clamp(ceil(w - 0.5), -4, 3)  (== jnp argmin, first-index ties)
// W = randn*0.1 -> nonzero quantized entries need |w| >= 5 sigma -> nnz ~ 10.
//
// Two kernels, no separate scatter pass:
//   k_quant:    pure-read stream over W (64 MB), collect nonzero entries.
//   k_fill_fix: each block OWNS R rows of out. Writes bias (pure 128 MB write
//               stream), __syncthreads, then applies all nnz corrections to
//               its own rows (fixup RMWs hit L1/L2 — lines just written).
//               No cross-block races -> no third kernel, no DRAM atomics.
//               nnz > NNZ_CAP: per-block owned-rows dense GEMM (safety net).
//               Last-finishing block resets the counter for the next replay.
// ---------------------------------------------------------------------------

#define NNZ_CAP (1 << 20)   // 1M entries = 8 MB scratch
#define ROWS_PB 4           // rows owned per k_fill_fix block

__device__ int          g_nnz;               // zero-init; reset by k_fill_fix
__device__ unsigned int g_done;              // ticket for last-block reset
__device__ unsigned int g_eidx[NNZ_CAP];     // o*IN + i
__device__ float        g_eval[NNZ_CAP];     // quantized level (nonzero)

__device__ __forceinline__ float quant1(float w) {
    float q = ceilf(w - 0.5f);               // round-half-down, exact vs argmin
    return fmaxf(-4.0f, fminf(3.0f, q));
}

// ---- Kernel 1: pure-read quantize + collect --------------------------------
__global__ void k_quant(const float* __restrict__ weight, int IN, int OUT) {
    const unsigned Wn = (unsigned)OUT * (unsigned)IN;
    const unsigned W4 = Wn >> 2;
    const unsigned gid = blockIdx.x * blockDim.x + threadIdx.x;
    const unsigned stride = gridDim.x * blockDim.x;
    const float4* w4p = reinterpret_cast<const float4*>(weight);
    for (unsigned t = gid; t < W4; t += stride) {
        float4 w = __ldcs(&w4p[t]);          // streaming: no reuse
        float q0 = quant1(w.x), q1 = quant1(w.y);
        float q2 = quant1(w.z), q3 = quant1(w.w);
        if ((q0 != 0.f) | (q1 != 0.f) | (q2 != 0.f) | (q3 != 0.f)) {
            unsigned base = t << 2;
            if (q0 != 0.f) { int s = atomicAdd(&g_nnz, 1); if (s < NNZ_CAP) { g_eidx[s] = base + 0u; g_eval[s] = q0; } }
            if (q1 != 0.f) { int s = atomicAdd(&g_nnz, 1); if (s < NNZ_CAP) { g_eidx[s] = base + 1u; g_eval[s] = q1; } }
            if (q2 != 0.f) { int s = atomicAdd(&g_nnz, 1); if (s < NNZ_CAP) { g_eidx[s] = base + 2u; g_eval[s] = q2; } }
            if (q3 != 0.f) { int s = atomicAdd(&g_nnz, 1); if (s < NNZ_CAP) { g_eidx[s] = base + 3u; g_eval[s] = q3; } }
        }
    }
    unsigned tail = Wn & 3u;                 // no-op for 4096-divisible shapes
    if (gid < tail) {
        unsigned e = (W4 << 2) + gid;
        float q = quant1(weight[e]);
        if (q != 0.f) { int s = atomicAdd(&g_nnz, 1); if (s < NNZ_CAP) { g_eidx[s] = e; g_eval[s] = q; } }
    }
}

// ---- Kernel 2: owned-rows fill + fixup (+ guarded dense fallback) ----------
// grid = ceil(B / ROWS_PB), block = 256. Block b owns rows [b*R, b*R+R).
__global__ void k_fill_fix(const float* __restrict__ x,
                           const float* __restrict__ weight,
                           const float* __restrict__ bias,
                           float* __restrict__ out,
                           int IN, int OUT, int B) {
    const int nnz = g_nnz;
    const int r0 = blockIdx.x * ROWS_PB;
    const int nrows = min(ROWS_PB, B - r0);
    const int tid = threadIdx.x;

    if (nnz <= NNZ_CAP) {
        // ---- Phase A: pure bias fill of owned rows (streaming stores) ----
        if (nrows == ROWS_PB && (OUT & 3) == 0) {
            const unsigned OUT4 = (unsigned)OUT >> 2;
            const unsigned mask_ok = ((OUT4 & (OUT4 - 1u)) == 0u);
            const unsigned mask = OUT4 - 1u;
            const float4* b4 = reinterpret_cast<const float4*>(bias);
            float4* o4 = reinterpret_cast<float4*>(out) + (size_t)r0 * OUT4;
            const unsigned n4 = (unsigned)ROWS_PB * OUT4;
            if (mask_ok) {
                for (unsigned t = tid; t < n4; t += blockDim.x)
                    __stcs(&o4[t], __ldg(&b4[t & mask]));
            } else {
                for (unsigned t = tid; t < n4; t += blockDim.x)
                    __stcs(&o4[t], __ldg(&b4[t % OUT4]));
            }
        } else {                              // generic scalar path (tails)
            const unsigned n = (unsigned)nrows * (unsigned)OUT;
            float* ob = out + (size_t)r0 * OUT;
            for (unsigned t = tid; t < n; t += blockDim.x)
                ob[t] = __ldg(&bias[t % (unsigned)OUT]);
        }

        if (nnz > 0) {
            __syncthreads();   // order fill stores before fixup (block scope)

            // ---- Phase B: fixups for owned rows; lines are L1/L2-hot ----
            // item = e * nrows + r ; atomicAdd handles duplicate-o entries.
            const int items = nnz * nrows;
            for (int t = tid; t < items; t += blockDim.x) {
                const int e = t / nrows;
                const int r = t - e * nrows;
                const unsigned idx = __ldg(&g_eidx[e]);
                const float v = __ldg(&g_eval[e]);
                const unsigned o = idx / (unsigned)IN;   // shifts for pow2 IN
                const unsigned i = idx % (unsigned)IN;
                const int b = r0 + r;
                atomicAdd(&out[(size_t)b * OUT + o],
                          v * __ldg(&x[(size_t)b * IN + i]));
            }
        }
    } else {
        // ---- Dense safety net: owned-rows GEMM (never taken on dataset) ----
        __shared__ float xs[ROWS_PB][1024];
        // init owned rows with bias
        {
            const unsigned n = (unsigned)nrows * (unsigned)OUT;
            float* ob = out + (size_t)r0 * OUT;
            for (unsigned t = tid; t < n; t += blockDim.x)
                ob[t] = __ldg(&bias[t % (unsigned)OUT]);
        }
        __syncthreads();
        for (int k0 = 0; k0 < IN; k0 += 1024) {
            const int kc = min(1024, IN - k0);
            for (int t = tid; t < nrows * kc; t += blockDim.x) {
                int r = t / kc, kk = t - r * kc;
                xs[r][kk] = x[(size_t)(r0 + r) * IN + k0 + kk];
            }
            __syncthreads();
            for (int o = tid; o < OUT; o += blockDim.x) {
                float acc[ROWS_PB];
                #pragma unroll
                for (int r = 0; r < ROWS_PB; r++) acc[r] = 0.f;
                const float* wrow = weight + (size_t)o * IN + k0;
                for (int kk = 0; kk < kc; kk++) {
                    float wq = quant1(wrow[kk]);
                    if (wq != 0.f) {
                        #pragma unroll
                        for (int r = 0; r < ROWS_PB; r++)
                            acc[r] += xs[r][kk] * wq;
                    }
                }
                for (int r = 0; r < nrows; r++)
                    out[(size_t)(r0 + r) * OUT + o] += acc[r];
            }
            __syncthreads();
        }
    }

    // Last-finishing block resets the counter for the next graph replay.
    // Every block read g_nnz before incrementing the ticket.
    __syncthreads();
    if (tid == 0) {
        unsigned t = atomicAdd(&g_done, 1u);
        if (t == gridDim.x - 1) { g_done = 0u; g_nnz = 0; }
    }
}

extern "C" void kernel_launch(void* const* d_in, const int* in_sizes, int n_in,
                              void* d_out, int out_size) {
    const float* x      = (const float*)d_in[0];   // [B, IN]
    const float* weight = (const float*)d_in[1];   // [OUT, IN]
    const float* bias   = (const float*)d_in[2];   // [OUT]
    float* out = (float*)d_out;                    // [B, OUT]

    int OUT = in_sizes[2];
    int IN  = in_sizes[1] / OUT;
    int B   = in_sizes[0] / IN;

    k_quant<<<1184, 256>>>(weight, IN, OUT);

    int fblocks = (B + ROWS_PB - 1) / ROWS_PB;     // 2048 for B=8192
    k_fill_fix<<<fblocks, 256>>>(x, weight, bias, out, IN, OUT, B);
}